// round 4
// baseline (speedup 1.0000x reference)
#include <cuda_runtime.h>
#include <cuda_bf16.h>
#include <cstdint>

#define BB   8
#define NCAM 6
#define DD   41
#define FHH  8
#define FWW  22
#define CC   64
#define NXY  200
#define PTS_PER_CAM (DD*FHH*FWW)          /* 7216 */
#define NPTS (BB*NCAM*PTS_PER_CAM)        /* 346368 */
#define GRID_CELLS (BB*NXY*NXY)           /* 320000 */

// Scratch: channel-last voxel grid [B,200,200,C]  (81.92 MB, static device alloc)
// INVARIANT: all-zero at the start of every kernel_launch call. Static init
// zeroes it; transpose_out re-zeroes every touched cell after reading it.
__device__ float g_scratch[(size_t)GRID_CELLS * CC];
// Per-cell touched flag. INVARIANT: all-zero at call start; scatter sets,
// transpose_out reads + clears.
__device__ unsigned g_count[GRID_CELLS];
// Per-camera fused params: inv(post_rots)[9], post_trans[3], combine[9], trans[3]
__device__ float g_cam[BB * NCAM][24];

// ---------------------------------------------------------------------------
// Parallel camera setup: one thread per (camera, element 0..8).
// Thread (cam, j) computes inv(post_rots)[j] and combine[j] = (rots @ inv(intrins))[j]
// via adjugate/det in double. Short dependency chains, all 432 threads parallel.
__device__ __forceinline__ double det3(const double* a) {
    return a[0]*(a[4]*a[8] - a[5]*a[7])
         + a[1]*(a[5]*a[6] - a[3]*a[8])
         + a[2]*(a[3]*a[7] - a[4]*a[6]);
}
// inverse element [r][c] * det  (cyclic-permutation cofactor, sign-free form)
__device__ __forceinline__ double adjel(const double* a, int r, int c) {
    int c1 = (c + 1) % 3, c2 = (c + 2) % 3;
    int r1 = (r + 1) % 3, r2 = (r + 2) % 3;
    return a[c1*3 + r1] * a[c2*3 + r2] - a[c1*3 + r2] * a[c2*3 + r1];
}

__global__ void cam_setup(const float* __restrict__ rots,
                          const float* __restrict__ trans,
                          const float* __restrict__ intrins,
                          const float* __restrict__ post_rots,
                          const float* __restrict__ post_trans) {
    int t = threadIdx.x;                 // 0..511
    int cam = t / 9;
    int j   = t - cam * 9;
    if (cam >= BB * NCAM) return;
    int r = j / 3, c = j - r * 3;

    double pr[9], in[9];
    #pragma unroll
    for (int k = 0; k < 9; k++) pr[k] = post_rots[cam*9 + k];
    #pragma unroll
    for (int k = 0; k < 9; k++) in[k] = intrins[cam*9 + k];

    float* cp = g_cam[cam];
    // inv(post_rots)[r][c]
    cp[j] = (float)(adjel(pr, r, c) / det3(pr));
    // combine[r][c] = sum_k rots[r][k] * inv(intrins)[k][c]
    double s = (double)rots[cam*9 + r*3 + 0] * adjel(in, 0, c)
             + (double)rots[cam*9 + r*3 + 1] * adjel(in, 1, c)
             + (double)rots[cam*9 + r*3 + 2] * adjel(in, 2, c);
    cp[12 + j] = (float)(s / det3(in));
    if (j < 3) {
        cp[9 + j]  = post_trans[cam*3 + j];
        cp[21 + j] = trans[cam*3 + j];
    }
}

// ---------------------------------------------------------------------------
// Fused voxelize + scatter-add. 16 threads per point (one float4 of channels
// each). All 16 lanes redundantly compute the point's voxel index — same warp
// issue cost as one lane (SIMT), no separate voxelize kernel / g_vox traffic.
__global__ void scatter(const float* __restrict__ x_feats) {
    int gid = blockIdx.x * blockDim.x + threadIdx.x;   // exact grid, no guard
    int point = gid >> 4;
    int c4    = gid & 15;

    int cam = point / PTS_PER_CAM;
    int r   = point - cam * PTS_PER_CAM;
    int d   = r / (FHH * FWW);
    int r2  = r - d * (FHH * FWW);
    int h   = r2 / FWW;
    int w   = r2 - h * FWW;

    const float* cp = g_cam[cam];
    const float XSTEP = 351.0f / 21.0f;   // matches f32 linspace step
    const float YSTEP = 127.0f / 7.0f;
    float fx = (float)w * XSTEP;
    float fy = (float)h * YSTEP;
    float fz = 4.0f + (float)d;

    float px = fx - cp[9];
    float py = fy - cp[10];
    float pz = fz - cp[11];
    // q = inv(post_rots) @ p   (fma chain, k-order accumulation)
    float q0 = fmaf(cp[2], pz, fmaf(cp[1], py, cp[0]*px));
    float q1 = fmaf(cp[5], pz, fmaf(cp[4], py, cp[3]*px));
    float q2 = fmaf(cp[8], pz, fmaf(cp[7], py, cp[6]*px));
    // unproject: (u*d, v*d, d)
    float r0 = q0 * q2;
    float r1 = q1 * q2;
    float r2v = q2;
    // geom = combine @ r + trans
    float g0 = fmaf(cp[14], r2v, fmaf(cp[13], r1, cp[12]*r0)) + cp[21];
    float g1 = fmaf(cp[17], r2v, fmaf(cp[16], r1, cp[15]*r0)) + cp[22];
    float g2 = fmaf(cp[20], r2v, fmaf(cp[19], r1, cp[18]*r0)) + cp[23];

    // quantize: (geom - (BX - DX/2)) / DX, truncate toward zero
    float v0 = (g0 + 50.0f) / 0.5f;
    float v1 = (g1 + 50.0f) / 0.5f;
    float v2 = (g2 + 10.0f) / 20.0f;
    int i0 = (int)v0;
    int i1 = (int)v1;
    int i2 = (int)v2;

    if (i0 < 0 || i0 >= NXY || i1 < 0 || i1 >= NXY || i2 != 0) return;
    int b   = cam / NCAM;
    int vox = (b * NXY + i0) * NXY + i1;

    if (c4 == 0) g_count[vox] = 1u;   // benign race: all writers store 1
    float4 f = reinterpret_cast<const float4*>(x_feats)[gid];
    float* dst = g_scratch + (unsigned)vox * CC + c4 * 4;   // < 2^31 bytes? 20.48M floats*4=82MB ok via 64-bit ptr add of 32-bit idx*4
    asm volatile("red.global.add.v4.f32 [%0], {%1,%2,%3,%4};"
                 :: "l"(dst), "f"(f.x), "f"(f.y), "f"(f.z), "f"(f.w)
                 : "memory");
}

// ---------------------------------------------------------------------------
// Transpose [B,200(x),200(y),C] -> out [B,C,200(x),200(y)].
// Per-cell skip: untouched cells contribute constant zero without any scratch
// read or re-zero. Touched cells are read once and zeroed behind the read
// (maintains the all-zero invariant). g_count is always cleared.
// All addressing in 32-bit (out: 20.48M elems, scratch: 5.12M float4s).
__global__ void transpose_out(float* __restrict__ out) {
    __shared__ float tile[32][65];
    __shared__ unsigned s_flag[32];
    __shared__ int s_touched;
    int tid = threadIdx.x;               // 256 threads
    int bx  = blockIdx.y;                // b*200 + x
    int y0  = blockIdx.x * 32;
    int b = bx / NXY;
    int x = bx - b * NXY;
    int cellbase = bx * NXY;

    if (tid < 32) {
        int y = y0 + tid;
        unsigned f = 0u;
        if (y < NXY) {
            f = g_count[cellbase + y];
            if (f) g_count[cellbase + y] = 0u;
        }
        s_flag[tid] = f;
        unsigned m = __ballot_sync(0xffffffffu, f != 0u);
        if (tid == 0) s_touched = (m != 0u);
    }
    __syncthreads();

    int lane = tid & 31;
    int warp = tid >> 5;                 // 0..7
    int cgrp = lane >> 3;                // 0..3
    int yseg = lane & 7;                 // 0..7
    int yg4  = y0 + yseg * 4;            // float4-aligned y

    float4* out4 = reinterpret_cast<float4*>(out);

    if (s_touched) {
        // Load 32y x 64c tile as float4; skip + keep-zero for untouched cells.
        float4* srcbase = reinterpret_cast<float4*>(g_scratch) + (unsigned)cellbase * 16;
        int c4  = tid & 15;
        int ylo = tid >> 4;              // 0..15
        #pragma unroll
        for (int i = 0; i < 2; i++) {
            int y  = ylo + 16 * i;
            int yg = y0 + y;
            if (yg < NXY) {
                float4 v = make_float4(0.f, 0.f, 0.f, 0.f);
                if (s_flag[y]) {
                    v = srcbase[yg * 16 + c4];
                    srcbase[yg * 16 + c4] = make_float4(0.f, 0.f, 0.f, 0.f);
                }
                tile[y][c4 * 4 + 0] = v.x;
                tile[y][c4 * 4 + 1] = v.y;
                tile[y][c4 * 4 + 2] = v.z;
                tile[y][c4 * 4 + 3] = v.w;
            }
        }
        __syncthreads();
        if (yg4 < NXY) {
            #pragma unroll
            for (int j = 0; j < 2; j++) {
                int c = warp * 4 + cgrp + j * 32;
                int yl = yseg * 4;
                float4 v;
                v.x = tile[yl + 0][c];
                v.y = tile[yl + 1][c];
                v.z = tile[yl + 2][c];
                v.w = tile[yl + 3][c];
                unsigned o4 = ((((unsigned)b * CC + c) * NXY + x) * NXY + yg4) >> 2;
                out4[o4] = v;
            }
        }
    } else {
        if (yg4 < NXY) {
            float4 z = make_float4(0.f, 0.f, 0.f, 0.f);
            #pragma unroll
            for (int j = 0; j < 2; j++) {
                int c = warp * 4 + cgrp + j * 32;
                unsigned o4 = ((((unsigned)b * CC + c) * NXY + x) * NXY + yg4) >> 2;
                out4[o4] = z;
            }
        }
    }
}

// ---------------------------------------------------------------------------
extern "C" void kernel_launch(void* const* d_in, const int* in_sizes, int n_in,
                              void* d_out, int out_size) {
    const float* x_feats    = (const float*)d_in[0];
    const float* rots       = (const float*)d_in[1];
    const float* trans      = (const float*)d_in[2];
    const float* intrins    = (const float*)d_in[3];
    const float* post_rots  = (const float*)d_in[4];
    const float* post_trans = (const float*)d_in[5];
    float* out = (float*)d_out;

    cam_setup<<<1, 512>>>(rots, trans, intrins, post_rots, post_trans);
    scatter<<<NPTS * 16 / 256, 256>>>(x_feats);
    transpose_out<<<dim3(7, BB * NXY), 256>>>(out);
}

// round 5
// speedup vs baseline: 1.0577x; 1.0577x over previous
#include <cuda_runtime.h>
#include <cuda_bf16.h>
#include <cstdint>

#define BB   8
#define NCAM 6
#define DD   41
#define FHH  8
#define FWW  22
#define CC   64
#define NXY  200
#define PTS_PER_CAM (DD*FHH*FWW)          /* 7216 */
#define NPTS (BB*NCAM*PTS_PER_CAM)        /* 346368 */
#define GRID_CELLS (BB*NXY*NXY)           /* 320000 */
#define NCAMS (BB*NCAM)                   /* 48 */

// Scratch: channel-last voxel grid [B,200,200,C]  (81.92 MB, static device alloc)
// INVARIANT: all-zero at the start of every kernel_launch call. Static init
// zeroes it; transpose_out re-zeroes every touched cell after reading it.
__device__ float g_scratch[(size_t)GRID_CELLS * CC];
// Per-cell touched flag. INVARIANT: all-zero at call start; scatter sets,
// transpose_out reads + clears.
__device__ unsigned g_count[GRID_CELLS];
// Per-camera fused params: inv(post_rots)[9], post_trans[3], combine[9], trans[3]
__device__ float g_cam[NCAMS][24];

// ---------------------------------------------------------------------------
// Camera setup, FP64-lean: 96 threads, one 3x3 inverse each, NO f64 divides.
// Reciprocal of the determinant = f32 rcp estimate + 2 double Newton steps
// (rel err < 1 double ulp — invisible after the final cast to f32).
__device__ __forceinline__ double rcp_newton(double d) {
    double r = (double)__frcp_rn((float)d);
    double e = fma(-d, r, 1.0);  r = fma(r, e, r);   // ~2^-46
    e        = fma(-d, r, 1.0);  r = fma(r, e, r);   // < ulp
    return r;
}

__global__ void cam_setup(const float* __restrict__ rots,
                          const float* __restrict__ trans,
                          const float* __restrict__ intrins,
                          const float* __restrict__ post_rots,
                          const float* __restrict__ post_trans) {
    __shared__ double sik[NCAMS][9];     // inv(intrins)
    int t = threadIdx.x;                 // 0..95
    int role = t / NCAMS;                // 0: post_rots, 1: intrins
    int cam  = t - role * NCAMS;

    if (t < 2 * NCAMS) {
        const float* src = (role == 0 ? post_rots : intrins) + cam * 9;
        double a[9];
        #pragma unroll
        for (int k = 0; k < 9; k++) a[k] = src[k];
        double det = a[0]*(a[4]*a[8] - a[5]*a[7])
                   + a[1]*(a[5]*a[6] - a[3]*a[8])
                   + a[2]*(a[3]*a[7] - a[4]*a[6]);
        double id = rcp_newton(det);
        // inv[r][c] = cofactor(a, c, r) * id   (adjugate, cyclic form)
        #pragma unroll
        for (int r = 0; r < 3; r++) {
            #pragma unroll
            for (int c = 0; c < 3; c++) {
                int c1 = (c + 1) % 3, c2 = (c + 2) % 3;
                int r1 = (r + 1) % 3, r2 = (r + 2) % 3;
                double adj = a[c1*3 + r1] * a[c2*3 + r2]
                           - a[c1*3 + r2] * a[c2*3 + r1];
                double v = adj * id;
                if (role == 0) g_cam[cam][r*3 + c] = (float)v;
                else           sik[cam][r*3 + c]   = v;
            }
        }
        if (role == 0) {
            #pragma unroll
            for (int j = 0; j < 3; j++) {
                g_cam[cam][9 + j]  = post_trans[cam*3 + j];
                g_cam[cam][21 + j] = trans[cam*3 + j];
            }
        }
    }
    __syncthreads();
    // combine = rots @ inv(intrins), 48 threads, 27 independent DFMA each
    if (t < NCAMS) {
        const float* rt = rots + t * 9;
        #pragma unroll
        for (int r = 0; r < 3; r++) {
            #pragma unroll
            for (int c = 0; c < 3; c++) {
                double s = (double)rt[r*3+0] * sik[t][0*3 + c]
                         + (double)rt[r*3+1] * sik[t][1*3 + c]
                         + (double)rt[r*3+2] * sik[t][2*3 + c];
                g_cam[t][12 + r*3 + c] = (float)s;
            }
        }
    }
}

// ---------------------------------------------------------------------------
// Fused voxelize + scatter-add. 16 threads per point (one float4 of channels
// each). All 16 lanes redundantly compute the point's voxel index — same warp
// issue cost as one lane (SIMT), no separate voxelize kernel / g_vox traffic.
__global__ void scatter(const float* __restrict__ x_feats) {
    int gid = blockIdx.x * blockDim.x + threadIdx.x;   // exact grid, no guard
    int point = gid >> 4;
    int c4    = gid & 15;

    int cam = point / PTS_PER_CAM;
    int r   = point - cam * PTS_PER_CAM;
    int d   = r / (FHH * FWW);
    int r2  = r - d * (FHH * FWW);
    int h   = r2 / FWW;
    int w   = r2 - h * FWW;

    const float* cp = g_cam[cam];
    const float XSTEP = 351.0f / 21.0f;   // matches f32 linspace step
    const float YSTEP = 127.0f / 7.0f;
    float fx = (float)w * XSTEP;
    float fy = (float)h * YSTEP;
    float fz = 4.0f + (float)d;

    float px = fx - cp[9];
    float py = fy - cp[10];
    float pz = fz - cp[11];
    // q = inv(post_rots) @ p   (fma chain, k-order accumulation)
    float q0 = fmaf(cp[2], pz, fmaf(cp[1], py, cp[0]*px));
    float q1 = fmaf(cp[5], pz, fmaf(cp[4], py, cp[3]*px));
    float q2 = fmaf(cp[8], pz, fmaf(cp[7], py, cp[6]*px));
    // unproject: (u*d, v*d, d)
    float r0 = q0 * q2;
    float r1 = q1 * q2;
    float r2v = q2;
    // geom = combine @ r + trans
    float g0 = fmaf(cp[14], r2v, fmaf(cp[13], r1, cp[12]*r0)) + cp[21];
    float g1 = fmaf(cp[17], r2v, fmaf(cp[16], r1, cp[15]*r0)) + cp[22];
    float g2 = fmaf(cp[20], r2v, fmaf(cp[19], r1, cp[18]*r0)) + cp[23];

    // quantize: (geom - (BX - DX/2)) / DX, truncate toward zero
    float v0 = (g0 + 50.0f) / 0.5f;
    float v1 = (g1 + 50.0f) / 0.5f;
    float v2 = (g2 + 10.0f) / 20.0f;
    int i0 = (int)v0;
    int i1 = (int)v1;
    int i2 = (int)v2;

    if (i0 < 0 || i0 >= NXY || i1 < 0 || i1 >= NXY || i2 != 0) return;
    int b   = cam / NCAM;
    int vox = (b * NXY + i0) * NXY + i1;

    if (c4 == 0) g_count[vox] = 1u;   // benign race: all writers store 1
    float4 f = reinterpret_cast<const float4*>(x_feats)[gid];
    float* dst = g_scratch + (unsigned)vox * CC + c4 * 4;
    asm volatile("red.global.add.v4.f32 [%0], {%1,%2,%3,%4};"
                 :: "l"(dst), "f"(f.x), "f"(f.y), "f"(f.z), "f"(f.w)
                 : "memory");
}

// ---------------------------------------------------------------------------
// Transpose [B,200(x),200(y),C] -> out [B,C,200(x),200(y)].
// Per-cell skip: untouched cells contribute constant zero without any scratch
// read or re-zero. Touched cells are read once and zeroed behind the read
// (maintains the all-zero invariant). g_count is always cleared.
// All addressing in 32-bit (out: 20.48M elems, scratch: 5.12M float4s).
__global__ void transpose_out(float* __restrict__ out) {
    __shared__ float tile[32][65];
    __shared__ unsigned s_flag[32];
    __shared__ int s_touched;
    int tid = threadIdx.x;               // 256 threads
    int bx  = blockIdx.y;                // b*200 + x
    int y0  = blockIdx.x * 32;
    int b = bx / NXY;
    int x = bx - b * NXY;
    int cellbase = bx * NXY;

    if (tid < 32) {
        int y = y0 + tid;
        unsigned f = 0u;
        if (y < NXY) {
            f = g_count[cellbase + y];
            if (f) g_count[cellbase + y] = 0u;
        }
        s_flag[tid] = f;
        unsigned m = __ballot_sync(0xffffffffu, f != 0u);
        if (tid == 0) s_touched = (m != 0u);
    }
    __syncthreads();

    int lane = tid & 31;
    int warp = tid >> 5;                 // 0..7
    int cgrp = lane >> 3;                // 0..3
    int yseg = lane & 7;                 // 0..7
    int yg4  = y0 + yseg * 4;            // float4-aligned y

    float4* out4 = reinterpret_cast<float4*>(out);

    if (s_touched) {
        // Load 32y x 64c tile as float4; skip + keep-zero for untouched cells.
        float4* srcbase = reinterpret_cast<float4*>(g_scratch) + (unsigned)cellbase * 16;
        int c4  = tid & 15;
        int ylo = tid >> 4;              // 0..15
        #pragma unroll
        for (int i = 0; i < 2; i++) {
            int y  = ylo + 16 * i;
            int yg = y0 + y;
            if (yg < NXY) {
                float4 v = make_float4(0.f, 0.f, 0.f, 0.f);
                if (s_flag[y]) {
                    v = srcbase[yg * 16 + c4];
                    srcbase[yg * 16 + c4] = make_float4(0.f, 0.f, 0.f, 0.f);
                }
                tile[y][c4 * 4 + 0] = v.x;
                tile[y][c4 * 4 + 1] = v.y;
                tile[y][c4 * 4 + 2] = v.z;
                tile[y][c4 * 4 + 3] = v.w;
            }
        }
        __syncthreads();
        if (yg4 < NXY) {
            #pragma unroll
            for (int j = 0; j < 2; j++) {
                int c = warp * 4 + cgrp + j * 32;
                int yl = yseg * 4;
                float4 v;
                v.x = tile[yl + 0][c];
                v.y = tile[yl + 1][c];
                v.z = tile[yl + 2][c];
                v.w = tile[yl + 3][c];
                unsigned o4 = ((((unsigned)b * CC + c) * NXY + x) * NXY + yg4) >> 2;
                out4[o4] = v;
            }
        }
    } else {
        if (yg4 < NXY) {
            float4 z = make_float4(0.f, 0.f, 0.f, 0.f);
            #pragma unroll
            for (int j = 0; j < 2; j++) {
                int c = warp * 4 + cgrp + j * 32;
                unsigned o4 = ((((unsigned)b * CC + c) * NXY + x) * NXY + yg4) >> 2;
                out4[o4] = z;
            }
        }
    }
}

// ---------------------------------------------------------------------------
extern "C" void kernel_launch(void* const* d_in, const int* in_sizes, int n_in,
                              void* d_out, int out_size) {
    const float* x_feats    = (const float*)d_in[0];
    const float* rots       = (const float*)d_in[1];
    const float* trans      = (const float*)d_in[2];
    const float* intrins    = (const float*)d_in[3];
    const float* post_rots  = (const float*)d_in[4];
    const float* post_trans = (const float*)d_in[5];
    float* out = (float*)d_out;

    cam_setup<<<1, 96>>>(rots, trans, intrins, post_rots, post_trans);
    scatter<<<NPTS * 16 / 256, 256>>>(x_feats);
    transpose_out<<<dim3(7, BB * NXY), 256>>>(out);
}